// round 1
// baseline (speedup 1.0000x reference)
#include <cuda_runtime.h>
#include <math.h>

// NT-Xent loss, fused. B=4096, D=512 (D hardcoded, B derived from in_sizes).
// loss_i = log(sum_{j!=i} exp(sim_ij / T) + 1e-8) - sim_{i,partner}/T
// out = mean_i loss_i,  sim_ij = dot(zn_i, zn_j), zn = row-normalized [z_i; z_j].

#define D 512
#define MAXN 8192
#define TEMP_INV 2.0f  // 1 / 0.5

#define TM 64
#define TN 64
#define TK 16
#define LDP 68  // padded leading dim for smem tiles (16B-aligned rows, conflict-reduced)

__device__ float g_zn[(size_t)MAXN * D];
__device__ float g_denom[MAXN];
__device__ float g_loss[MAXN];

// ---------------------------------------------------------------------------
// 1) Row-normalize z = [z_i ; z_j] -> g_zn. One 128-thread block per row.
// ---------------------------------------------------------------------------
__global__ void normalize_kernel(const float* __restrict__ zi,
                                 const float* __restrict__ zj, int B) {
    int row = blockIdx.x;
    const float* src = (row < B) ? (zi + (size_t)row * D)
                                 : (zj + (size_t)(row - B) * D);
    int t = threadIdx.x;  // 0..127, each thread owns 4 contiguous floats
    float4 v = *(const float4*)(src + t * 4);
    float ss = v.x * v.x + v.y * v.y + v.z * v.z + v.w * v.w;

    __shared__ float red[128];
    red[t] = ss;
    __syncthreads();
#pragma unroll
    for (int s = 64; s > 0; s >>= 1) {
        if (t < s) red[t] += red[t + s];
        __syncthreads();
    }
    // norm product >> 1e-8 eps here, so plain 1/norm matches reference
    float rinv = 1.0f / sqrtf(red[0]);
    float4 o = make_float4(v.x * rinv, v.y * rinv, v.z * rinv, v.w * rinv);
    *(float4*)(g_zn + (size_t)row * D + t * 4) = o;
}

// ---------------------------------------------------------------------------
// 2) Fused GEMM + exp + row-sum. Each CTA owns TM=64 rows, loops over all N
//    columns in TN=64 tiles; 256 threads, 4x4 micro-tile per thread.
//    Row sums kept in registers (deterministic, no atomics).
// ---------------------------------------------------------------------------
__global__ void __launch_bounds__(256) denom_kernel(int N) {
    __shared__ float As[TK][LDP];
    __shared__ float Bs[TK][LDP];
    __shared__ float red[TM][17];

    const float* __restrict__ zn = g_zn;
    int t = threadIdx.x;
    int tx = t & 15;        // 0..15 -> column group
    int ty = t >> 4;        // 0..15 -> row group
    int lr = t >> 2;        // 0..63 loader row
    int lq = t & 3;         // 0..3  loader quad (float4 within 16-wide k chunk)
    int rowBase = blockIdx.x * TM;

    float rowsum[4] = {0.f, 0.f, 0.f, 0.f};

    for (int colBase = 0; colBase < N; colBase += TN) {
        float acc[4][4];
#pragma unroll
        for (int r = 0; r < 4; r++)
#pragma unroll
            for (int c = 0; c < 4; c++) acc[r][c] = 0.f;

        for (int k0 = 0; k0 < D; k0 += TK) {
            float4 av = *(const float4*)(zn + (size_t)(rowBase + lr) * D + k0 + lq * 4);
            float4 bv = *(const float4*)(zn + (size_t)(colBase + lr) * D + k0 + lq * 4);
            As[lq * 4 + 0][lr] = av.x;
            As[lq * 4 + 1][lr] = av.y;
            As[lq * 4 + 2][lr] = av.z;
            As[lq * 4 + 3][lr] = av.w;
            Bs[lq * 4 + 0][lr] = bv.x;
            Bs[lq * 4 + 1][lr] = bv.y;
            Bs[lq * 4 + 2][lr] = bv.z;
            Bs[lq * 4 + 3][lr] = bv.w;
            __syncthreads();

#pragma unroll
            for (int k = 0; k < TK; k++) {
                float4 a = *(const float4*)(&As[k][ty * 4]);
                float4 b = *(const float4*)(&Bs[k][tx * 4]);
                acc[0][0] += a.x * b.x; acc[0][1] += a.x * b.y;
                acc[0][2] += a.x * b.z; acc[0][3] += a.x * b.w;
                acc[1][0] += a.y * b.x; acc[1][1] += a.y * b.y;
                acc[1][2] += a.y * b.z; acc[1][3] += a.y * b.w;
                acc[2][0] += a.z * b.x; acc[2][1] += a.z * b.y;
                acc[2][2] += a.z * b.z; acc[2][3] += a.z * b.w;
                acc[3][0] += a.w * b.x; acc[3][1] += a.w * b.y;
                acc[3][2] += a.w * b.z; acc[3][3] += a.w * b.w;
            }
            __syncthreads();
        }

        // epilogue: exp and accumulate row sums, skipping the diagonal (mask)
#pragma unroll
        for (int r = 0; r < 4; r++) {
            int grow = rowBase + ty * 4 + r;
#pragma unroll
            for (int c = 0; c < 4; c++) {
                int gcol = colBase + tx * 4 + c;
                float e = __expf(acc[r][c] * TEMP_INV);
                if (grow != gcol) rowsum[r] += e;
            }
        }
    }

    // reduce rowsum across the 16 tx column-groups (fixed order -> deterministic)
#pragma unroll
    for (int r = 0; r < 4; r++) red[ty * 4 + r][tx] = rowsum[r];
    __syncthreads();
    if (t < TM) {
        float s = 0.f;
#pragma unroll
        for (int j = 0; j < 16; j++) s += red[t][j];
        g_denom[rowBase + t] = s;
    }
}

// ---------------------------------------------------------------------------
// 3) Positives + per-row loss. One warp per row.
// ---------------------------------------------------------------------------
__global__ void loss_kernel(int B) {
    int warp = (blockIdx.x * blockDim.x + threadIdx.x) >> 5;
    int lane = threadIdx.x & 31;
    int N = 2 * B;
    if (warp >= N) return;
    int p = (warp < B) ? (warp + B) : (warp - B);
    const float* a = g_zn + (size_t)warp * D;
    const float* b = g_zn + (size_t)p * D;
    float dot = 0.f;
#pragma unroll
    for (int q = 0; q < D / (32 * 4); q++) {
        float4 va = *(const float4*)(a + (q * 32 + lane) * 4);
        float4 vb = *(const float4*)(b + (q * 32 + lane) * 4);
        dot += va.x * vb.x + va.y * vb.y + va.z * vb.z + va.w * vb.w;
    }
#pragma unroll
    for (int o = 16; o > 0; o >>= 1) dot += __shfl_xor_sync(0xffffffffu, dot, o);
    if (lane == 0)
        g_loss[warp] = logf(g_denom[warp] + 1e-8f) - dot * TEMP_INV;
}

// ---------------------------------------------------------------------------
// 4) Deterministic mean over N losses, single block.
// ---------------------------------------------------------------------------
__global__ void mean_kernel(float* __restrict__ out, int N) {
    __shared__ float red[256];
    int t = threadIdx.x;
    float s = 0.f;
    for (int i = t; i < N; i += 256) s += g_loss[i];
    red[t] = s;
    __syncthreads();
#pragma unroll
    for (int st = 128; st > 0; st >>= 1) {
        if (t < st) red[t] += red[t + st];
        __syncthreads();
    }
    if (t == 0) out[0] = red[0] / (float)N;
}

// ---------------------------------------------------------------------------
extern "C" void kernel_launch(void* const* d_in, const int* in_sizes, int n_in,
                              void* d_out, int out_size) {
    const float* zi = (const float*)d_in[0];
    const float* zj = (const float*)d_in[1];
    int B = in_sizes[0] / D;   // 4096
    int N = 2 * B;             // 8192

    normalize_kernel<<<N, 128>>>(zi, zj, B);
    denom_kernel<<<N / TM, 256>>>(N);
    loss_kernel<<<(N * 32 + 255) / 256, 256>>>(B);
    mean_kernel<<<1, 256>>>((float*)d_out, N);
}

// round 3
// speedup vs baseline: 14.4564x; 14.4564x over previous
#include <cuda_runtime.h>
#include <cuda_bf16.h>
#include <math.h>
#include <stdint.h>

// NT-Xent loss. B=4096, D=512. Fused bf16 HMMA (mma.sync) sim-GEMM with
// exp + row-sum epilogue in registers. Positives in fp32.

#define D 512
#define MAXN 8192
#define TEMP_INV 2.0f

#define TM 128       // rows per CTA
#define TNC 128      // cols per tile
#define KCHUNK 128   // bf16 K elems per streamed B chunk (4 chunks per tile)
#define NTILES 32    // col tiles per CTA (half of 8192 / 128)
#define KCS 4        // k-chunks per tile
#define TOTAL_ITS (NTILES * KCS)

// SMEM layout (dynamic)
#define SA_OFF 0
#define SA_BYTES (TM * D * 2)              // 131072
#define SB_OFF SA_BYTES
#define SB_BYTES (TNC * KCHUNK * 2)        // 32768 per buffer
#define SRED_OFF (SB_OFF + 2 * SB_BYTES)   // 196608
#define SMEM_TOTAL (SRED_OFF + 128 * 2 * 4)

__device__ float g_zn[(size_t)MAXN * D];
__device__ __nv_bfloat16 g_znb[(size_t)MAXN * D];
__device__ float g_denom2[2 * MAXN];
__device__ float g_loss[MAXN];

__device__ __forceinline__ uint32_t smem_u32(const void* p) {
    uint32_t a;
    asm("{ .reg .u64 t; cvta.to.shared.u64 t, %1; cvt.u32.u64 %0, t; }" : "=r"(a) : "l"(p));
    return a;
}
__device__ __forceinline__ void ldsm4(uint32_t* r, uint32_t addr) {
    asm volatile("ldmatrix.sync.aligned.m8n8.x4.shared.b16 {%0,%1,%2,%3}, [%4];"
                 : "=r"(r[0]), "=r"(r[1]), "=r"(r[2]), "=r"(r[3]) : "r"(addr));
}
__device__ __forceinline__ void mma_bf16(float* c, const uint32_t* a, const uint32_t* b) {
    asm volatile(
        "mma.sync.aligned.m16n8k16.row.col.f32.bf16.bf16.f32 "
        "{%0,%1,%2,%3}, {%4,%5,%6,%7}, {%8,%9}, {%0,%1,%2,%3};"
        : "+f"(c[0]), "+f"(c[1]), "+f"(c[2]), "+f"(c[3])
        : "r"(a[0]), "r"(a[1]), "r"(a[2]), "r"(a[3]), "r"(b[0]), "r"(b[1]));
}

// ---------------------------------------------------------------------------
// 1) normalize -> fp32 zn + bf16 znb
// ---------------------------------------------------------------------------
__global__ void normalize_kernel(const float* __restrict__ zi,
                                 const float* __restrict__ zj, int B) {
    int row = blockIdx.x;
    const float* src = (row < B) ? (zi + (size_t)row * D) : (zj + (size_t)(row - B) * D);
    int t = threadIdx.x;
    float4 v = *(const float4*)(src + t * 4);
    float ss = v.x * v.x + v.y * v.y + v.z * v.z + v.w * v.w;
    __shared__ float red[128];
    red[t] = ss;
    __syncthreads();
#pragma unroll
    for (int s = 64; s > 0; s >>= 1) {
        if (t < s) red[t] += red[t + s];
        __syncthreads();
    }
    float rinv = rsqrtf(red[0]);
    float4 o = make_float4(v.x * rinv, v.y * rinv, v.z * rinv, v.w * rinv);
    *(float4*)(g_zn + (size_t)row * D + t * 4) = o;
    __nv_bfloat16* ob = g_znb + (size_t)row * D + t * 4;
    ob[0] = __float2bfloat16(o.x);
    ob[1] = __float2bfloat16(o.y);
    ob[2] = __float2bfloat16(o.z);
    ob[3] = __float2bfloat16(o.w);
}

// ---------------------------------------------------------------------------
// 2) fused HMMA GEMM + exp row-sum. 128 CTAs = (64 rowTiles) x (2 col halves).
// ---------------------------------------------------------------------------
__device__ __forceinline__ void prefetchB(const __nv_bfloat16* __restrict__ znb,
                                          int colBase, int kc, uint32_t smemBuf, int tid) {
#pragma unroll
    for (int i = 0; i < 8; i++) {
        int idx = tid + i * 256;
        int n = idx >> 4;
        int c = idx & 15;
        const void* g = znb + (size_t)(colBase + n) * D + kc * KCHUNK + c * 8;
        uint32_t s = smemBuf + n * 256 + ((c ^ (n & 7)) << 4);
        asm volatile("cp.async.cg.shared.global [%0], [%1], 16;" :: "r"(s), "l"(g));
    }
    asm volatile("cp.async.commit_group;");
}

__global__ void __launch_bounds__(256, 1) denom_kernel() {
    extern __shared__ char smem[];
    const int tid = threadIdx.x;
    const int lane = tid & 31;
    const int wid = tid >> 5;
    const int warpM = wid & 3;   // 0..3 -> 32-row strip
    const int warpN = wid >> 2;  // 0..1 -> 64-col strip
    const int rowTile = blockIdx.x >> 1;
    const int half = blockIdx.x & 1;
    const int rowBase = rowTile * TM;
    const int colStart = half * (MAXN / 2);

    const __nv_bfloat16* __restrict__ znb = g_znb;
    uint32_t sA = smem_u32(smem) + SA_OFF;
    uint32_t sB = smem_u32(smem) + SB_OFF;
    float (*red)[2] = (float(*)[2])(smem + SRED_OFF);

    // Load persistent A tile [128 x 512 bf16], XOR-swizzled (16B-chunk ^ row&7).
#pragma unroll 8
    for (int idx = tid; idx < TM * 64; idx += 256) {
        int r = idx >> 6;
        int c = idx & 63;
        uint4 v = *(const uint4*)(znb + (size_t)(rowBase + r) * D + c * 8);
        *(uint4*)(smem + SA_OFF + r * 1024 + ((c ^ (r & 7)) << 4)) = v;
    }

    // per-lane ldmatrix address constants
    const int aRow = warpM * 32 + (lane & 15);            // + mt*16
    const uint32_t aBase = sA + aRow * 1024;
    const int aXor = aRow & 7;
    const int aC = lane >> 4;                             // chunk +0/+1
    const int bRow = warpN * 64 + (lane & 7) + ((lane >> 4) << 3);  // + bg*16
    const int bXor = bRow & 7;
    const int bC = (lane >> 3) & 1;                       // chunk +0/+1

    float acc[2][8][4];
#pragma unroll
    for (int mt = 0; mt < 2; mt++)
#pragma unroll
        for (int nt = 0; nt < 8; nt++)
#pragma unroll
            for (int j = 0; j < 4; j++) acc[mt][nt][j] = 0.f;
    float part[2][2] = {{0.f, 0.f}, {0.f, 0.f}};

    // prefetch first B chunk
    prefetchB(znb, colStart, 0, sB, tid);

    for (int it = 0; it < TOTAL_ITS; ++it) {
        int tile = it >> 2;
        int kc = it & 3;
        if (it + 1 < TOTAL_ITS) {
            int itn = it + 1;
            prefetchB(znb, colStart + (itn >> 2) * TNC, itn & 3,
                      sB + ((itn & 1) << 15), tid);
            asm volatile("cp.async.wait_group 1;");
        } else {
            asm volatile("cp.async.wait_group 0;");
        }
        __syncthreads();

        uint32_t bufB = sB + ((it & 1) << 15);
#pragma unroll
        for (int s = 0; s < 8; ++s) {
            uint32_t af[2][4];
#pragma unroll
            for (int mt = 0; mt < 2; mt++)
                ldsm4(af[mt], aBase + mt * 16384 +
                              (((kc * 16 + s * 2 + aC) ^ aXor) << 4));
#pragma unroll
            for (int bg = 0; bg < 4; bg++) {
                uint32_t bf[4];
                ldsm4(bf, bufB + (bRow + bg * 16) * 256 +
                          (((s * 2 + bC) ^ bXor) << 4));
#pragma unroll
                for (int mt = 0; mt < 2; mt++) {
                    mma_bf16(acc[mt][bg * 2], af[mt], bf);
                    mma_bf16(acc[mt][bg * 2 + 1], af[mt], bf + 2);
                }
            }
        }

        if (kc == 3) {
            // epilogue: exp + row-sum, skip diagonal; reset accumulators
            int colWBase = colStart + tile * TNC + warpN * 64 + (lane & 3) * 2;
#pragma unroll
            for (int mt = 0; mt < 2; mt++) {
                int r0 = rowBase + warpM * 32 + mt * 16 + (lane >> 2);
                int r1 = r0 + 8;
#pragma unroll
                for (int nt = 0; nt < 8; nt++) {
                    int c0 = colWBase + nt * 8;
                    float e0 = __expf(acc[mt][nt][0] * TEMP_INV);
                    float e1 = __expf(acc[mt][nt][1] * TEMP_INV);
                    float e2 = __expf(acc[mt][nt][2] * TEMP_INV);
                    float e3 = __expf(acc[mt][nt][3] * TEMP_INV);
                    part[mt][0] += (c0 != r0 ? e0 : 0.f) + (c0 + 1 != r0 ? e1 : 0.f);
                    part[mt][1] += (c0 != r1 ? e2 : 0.f) + (c0 + 1 != r1 ? e3 : 0.f);
                    acc[mt][nt][0] = 0.f; acc[mt][nt][1] = 0.f;
                    acc[mt][nt][2] = 0.f; acc[mt][nt][3] = 0.f;
                }
            }
        }
        __syncthreads();
    }

    // reduce partials: 4 threads (lane&3) share each row
#pragma unroll
    for (int mt = 0; mt < 2; mt++)
#pragma unroll
        for (int h = 0; h < 2; h++) {
            float p = part[mt][h];
            p += __shfl_xor_sync(0xffffffffu, p, 1);
            p += __shfl_xor_sync(0xffffffffu, p, 2);
            part[mt][h] = p;
        }
    if ((lane & 3) == 0) {
#pragma unroll
        for (int mt = 0; mt < 2; mt++)
#pragma unroll
            for (int h = 0; h < 2; h++) {
                int rl = warpM * 32 + mt * 16 + (lane >> 2) + 8 * h;
                red[rl][warpN] = part[mt][h];
            }
    }
    __syncthreads();
    if (tid < TM)
        g_denom2[half * MAXN + rowBase + tid] = red[tid][0] + red[tid][1];
}

// ---------------------------------------------------------------------------
// 3) positives (fp32) + per-row loss
// ---------------------------------------------------------------------------
__global__ void loss_kernel(int B) {
    int warp = (blockIdx.x * blockDim.x + threadIdx.x) >> 5;
    int lane = threadIdx.x & 31;
    int N = 2 * B;
    if (warp >= N) return;
    int p = (warp < B) ? (warp + B) : (warp - B);
    const float* a = g_zn + (size_t)warp * D;
    const float* b = g_zn + (size_t)p * D;
    float dot = 0.f;
#pragma unroll
    for (int q = 0; q < D / (32 * 4); q++) {
        float4 va = *(const float4*)(a + (q * 32 + lane) * 4);
        float4 vb = *(const float4*)(b + (q * 32 + lane) * 4);
        dot += va.x * vb.x + va.y * vb.y + va.z * vb.z + va.w * vb.w;
    }
#pragma unroll
    for (int o = 16; o > 0; o >>= 1) dot += __shfl_xor_sync(0xffffffffu, dot, o);
    if (lane == 0) {
        float denom = g_denom2[warp] + g_denom2[MAXN + warp];
        g_loss[warp] = logf(denom + 1e-8f) - dot * TEMP_INV;
    }
}

// ---------------------------------------------------------------------------
// 4) deterministic mean
// ---------------------------------------------------------------------------
__global__ void mean_kernel(float* __restrict__ out, int N) {
    __shared__ float red[256];
    int t = threadIdx.x;
    float s = 0.f;
    for (int i = t; i < N; i += 256) s += g_loss[i];
    red[t] = s;
    __syncthreads();
#pragma unroll
    for (int st = 128; st > 0; st >>= 1) {
        if (t < st) red[t] += red[t + st];
        __syncthreads();
    }
    if (t == 0) out[0] = red[0] / (float)N;
}

// ---------------------------------------------------------------------------
extern "C" void kernel_launch(void* const* d_in, const int* in_sizes, int n_in,
                              void* d_out, int out_size) {
    const float* zi = (const float*)d_in[0];
    const float* zj = (const float*)d_in[1];
    int B = in_sizes[0] / D;  // 4096
    int N = 2 * B;            // 8192

    cudaFuncSetAttribute(denom_kernel, cudaFuncAttributeMaxDynamicSharedMemorySize, SMEM_TOTAL);

    normalize_kernel<<<N, 128>>>(zi, zj, B);
    denom_kernel<<<N / TM * 2, 256, SMEM_TOTAL>>>();
    loss_kernel<<<(N * 32 + 255) / 256, 256>>>(B);
    mean_kernel<<<1, 256>>>((float*)d_out, N);
}

// round 4
// speedup vs baseline: 16.5502x; 1.1448x over previous
#include <cuda_runtime.h>
#include <cuda_bf16.h>
#include <math.h>
#include <stdint.h>

// NT-Xent loss. B=4096, D=512. Fused bf16 HMMA sim-GEMM with exp+row-sum
// epilogue. 148 persistent CTAs with static contiguous work partition.

#define D 512
#define MAXN 8192
#define TEMP_INV 2.0f
#define NCTA 148
#define NCHUNK 16          // column chunks per rowTile (512 cols each)
#define NITEMS (64 * NCHUNK)

#define TM 128             // rows per tile
#define TNC 128            // cols per col-tile
#define KCHUNK 128         // bf16 K per B stage

// SMEM layout
#define SA_OFF 0
#define SA_BYTES (TM * D * 2)            // 131072
#define SB_OFF SA_BYTES
#define SB_BYTES (TNC * KCHUNK * 2)      // 32768 per stage
#define NSTAGE 3
#define SRED_OFF (SB_OFF + NSTAGE * SB_BYTES)
#define SMEM_TOTAL (SRED_OFF + 128 * 2 * 4)   // 230400 B

__device__ __nv_bfloat16 g_znb[(size_t)MAXN * D];
__device__ float g_rinv[MAXN];
__device__ float g_part[NCHUNK * MAXN];
__device__ float g_loss[MAXN];

__device__ __forceinline__ uint32_t smem_u32(const void* p) {
    uint32_t a;
    asm("{ .reg .u64 t; cvta.to.shared.u64 t, %1; cvt.u32.u64 %0, t; }" : "=r"(a) : "l"(p));
    return a;
}
__device__ __forceinline__ void ldsm4(uint32_t* r, uint32_t addr) {
    asm volatile("ldmatrix.sync.aligned.m8n8.x4.shared.b16 {%0,%1,%2,%3}, [%4];"
                 : "=r"(r[0]), "=r"(r[1]), "=r"(r[2]), "=r"(r[3]) : "r"(addr));
}
__device__ __forceinline__ void mma_bf16(float* c, const uint32_t* a, const uint32_t* b) {
    asm volatile(
        "mma.sync.aligned.m16n8k16.row.col.f32.bf16.bf16.f32 "
        "{%0,%1,%2,%3}, {%4,%5,%6,%7}, {%8,%9}, {%0,%1,%2,%3};"
        : "+f"(c[0]), "+f"(c[1]), "+f"(c[2]), "+f"(c[3])
        : "r"(a[0]), "r"(a[1]), "r"(a[2]), "r"(a[3]), "r"(b[0]), "r"(b[1]));
}

// ---------------------------------------------------------------------------
// 1) normalize -> bf16 znb, inverse norms; zero g_part
// ---------------------------------------------------------------------------
__global__ void normalize_kernel(const float* __restrict__ zi,
                                 const float* __restrict__ zj, int B) {
    int row = blockIdx.x;
    const float* src = (row < B) ? (zi + (size_t)row * D) : (zj + (size_t)(row - B) * D);
    int t = threadIdx.x;
    float4 v = *(const float4*)(src + t * 4);
    float ss = v.x * v.x + v.y * v.y + v.z * v.z + v.w * v.w;
    __shared__ float red[128];
    red[t] = ss;
    __syncthreads();
#pragma unroll
    for (int s = 64; s > 0; s >>= 1) {
        if (t < s) red[t] += red[t + s];
        __syncthreads();
    }
    float rinv = rsqrtf(red[0]);
    __nv_bfloat16* ob = g_znb + (size_t)row * D + t * 4;
    ob[0] = __float2bfloat16(v.x * rinv);
    ob[1] = __float2bfloat16(v.y * rinv);
    ob[2] = __float2bfloat16(v.z * rinv);
    ob[3] = __float2bfloat16(v.w * rinv);
    if (t == 0) g_rinv[row] = rinv;
    if (t < NCHUNK) g_part[t * MAXN + row] = 0.0f;
}

// ---------------------------------------------------------------------------
// 2) fused HMMA GEMM + exp row-sum, 148 CTAs, static contiguous item ranges.
// ---------------------------------------------------------------------------
__device__ __forceinline__ void prefetchB(const __nv_bfloat16* __restrict__ znb,
                                          int colBase, int kc, uint32_t smemBuf, int tid) {
#pragma unroll
    for (int i = 0; i < 8; i++) {
        int idx = tid + i * 256;
        int n = idx >> 4;
        int c = idx & 15;
        const void* g = znb + (size_t)(colBase + n) * D + kc * KCHUNK + c * 8;
        uint32_t s = smemBuf + n * 256 + ((c ^ (n & 7)) << 4);
        asm volatile("cp.async.cg.shared.global [%0], [%1], 16;" :: "r"(s), "l"(g));
    }
    asm volatile("cp.async.commit_group;");
}

__global__ void __launch_bounds__(256, 1) denom_kernel() {
    extern __shared__ char smem[];
    const int tid = threadIdx.x;
    const int lane = tid & 31;
    const int wid = tid >> 5;
    const int warpM = wid & 3;
    const int warpN = wid >> 2;
    const int cta = blockIdx.x;

    const __nv_bfloat16* __restrict__ znb = g_znb;
    uint32_t sA = smem_u32(smem) + SA_OFF;
    uint32_t sB = smem_u32(smem) + SB_OFF;
    float (*red)[2] = (float(*)[2])(smem + SRED_OFF);

    // per-lane ldmatrix constants
    const int aRow = warpM * 32 + (lane & 15);
    const uint32_t aBase = sA + aRow * 1024;
    const int aXor = aRow & 7;
    const int aC = lane >> 4;
    const int bRow = warpN * 64 + (lane & 7) + ((lane >> 4) << 3);
    const int bXor = bRow & 7;
    const int bC = (lane >> 3) & 1;

    int istart = (cta * NITEMS) / NCTA;
    const int iend = ((cta + 1) * NITEMS) / NCTA;

    while (istart < iend) {
        const int rowTile = istart >> 4;
        const int segEnd = min(iend, (rowTile + 1) << 4);
        const int chunk0 = istart & 15;
        const int nTiles = (segEnd - istart) * 4;   // 128-col tiles this segment
        const int rowBase = rowTile * TM;
        const int segCol = chunk0 * 512;

        // ---- load A tile [128 x 512 bf16] via cp.async, XOR-swizzled ----
        asm volatile("cp.async.wait_group 0;");   // drain any leftovers
        __syncthreads();                          // prior segment reads done
#pragma unroll 8
        for (int idx = tid; idx < TM * 64; idx += 256) {
            int r = idx >> 6;
            int c = idx & 63;
            const void* g = znb + (size_t)(rowBase + r) * D + c * 8;
            uint32_t s = sA + r * 1024 + ((c ^ (r & 7)) << 4);
            asm volatile("cp.async.cg.shared.global [%0], [%1], 16;" :: "r"(s), "l"(g));
        }
        asm volatile("cp.async.commit_group;");
        asm volatile("cp.async.wait_group 0;");
        __syncthreads();

        float acc[2][8][4];
#pragma unroll
        for (int mt = 0; mt < 2; mt++)
#pragma unroll
            for (int nt = 0; nt < 8; nt++)
#pragma unroll
                for (int j = 0; j < 4; j++) acc[mt][nt][j] = 0.f;
        float part[2][2] = {{0.f, 0.f}, {0.f, 0.f}};

        const int nIts = nTiles * 4;
        // prologue: stages 0,1
        prefetchB(znb, segCol, 0, sB, tid);
        if (nIts > 1) prefetchB(znb, segCol + ((1 >> 2) * TNC), 1 & 3, sB + SB_BYTES, tid);
        else asm volatile("cp.async.commit_group;");

        int buf = 0, pbuf = 2;
        for (int it = 0; it < nIts; ++it) {
            const int tile = it >> 2;
            const int kc = it & 3;
            asm volatile("cp.async.wait_group 1;");
            __syncthreads();

            // prefetch it+2
            int itn = it + 2;
            if (itn < nIts)
                prefetchB(znb, segCol + (itn >> 2) * TNC, itn & 3, sB + pbuf * SB_BYTES, tid);
            else
                asm volatile("cp.async.commit_group;");
            pbuf = (pbuf == 2) ? 0 : pbuf + 1;

            const uint32_t bufB = sB + buf * SB_BYTES;
            buf = (buf == 2) ? 0 : buf + 1;
#pragma unroll
            for (int s = 0; s < 8; ++s) {
                uint32_t af[2][4];
#pragma unroll
                for (int mt = 0; mt < 2; mt++)
                    ldsm4(af[mt], aBase + mt * 16384 + (((kc * 16 + s * 2 + aC) ^ aXor) << 4));
#pragma unroll
                for (int bg = 0; bg < 4; bg++) {
                    uint32_t bf[4];
                    ldsm4(bf, bufB + (bRow + bg * 16) * 256 + (((s * 2 + bC) ^ bXor) << 4));
#pragma unroll
                    for (int mt = 0; mt < 2; mt++) {
                        mma_bf16(acc[mt][bg * 2], af[mt], bf);
                        mma_bf16(acc[mt][bg * 2 + 1], af[mt], bf + 2);
                    }
                }
            }

            if (kc == 3) {
                // epilogue: exp + row-sum, skip diagonal; reset accumulators
                int colWBase = segCol + tile * TNC + warpN * 64 + (lane & 3) * 2;
#pragma unroll
                for (int mt = 0; mt < 2; mt++) {
                    int r0 = rowBase + warpM * 32 + mt * 16 + (lane >> 2);
                    int r1 = r0 + 8;
#pragma unroll
                    for (int nt = 0; nt < 8; nt++) {
                        int c0 = colWBase + nt * 8;
                        float e0 = __expf(acc[mt][nt][0] * TEMP_INV);
                        float e1 = __expf(acc[mt][nt][1] * TEMP_INV);
                        float e2 = __expf(acc[mt][nt][2] * TEMP_INV);
                        float e3 = __expf(acc[mt][nt][3] * TEMP_INV);
                        part[mt][0] += (c0 != r0 ? e0 : 0.f) + (c0 + 1 != r0 ? e1 : 0.f);
                        part[mt][1] += (c0 != r1 ? e2 : 0.f) + (c0 + 1 != r1 ? e3 : 0.f);
                        acc[mt][nt][0] = 0.f; acc[mt][nt][1] = 0.f;
                        acc[mt][nt][2] = 0.f; acc[mt][nt][3] = 0.f;
                    }
                }
            }
        }

        // ---- segment reduce: 4 lanes share each row ----
        __syncthreads();
#pragma unroll
        for (int mt = 0; mt < 2; mt++)
#pragma unroll
            for (int h = 0; h < 2; h++) {
                float p = part[mt][h];
                p += __shfl_xor_sync(0xffffffffu, p, 1);
                p += __shfl_xor_sync(0xffffffffu, p, 2);
                part[mt][h] = p;
            }
        if ((lane & 3) == 0) {
#pragma unroll
            for (int mt = 0; mt < 2; mt++)
#pragma unroll
                for (int h = 0; h < 2; h++) {
                    int rl = warpM * 32 + mt * 16 + (lane >> 2) + 8 * h;
                    red[rl][warpN] = part[mt][h];
                }
        }
        __syncthreads();
        if (tid < TM)
            g_part[chunk0 * MAXN + rowBase + tid] = red[tid][0] + red[tid][1];

        istart = segEnd;
    }
}

// ---------------------------------------------------------------------------
// 3) positives (fp32, from raw inputs) + per-row loss
// ---------------------------------------------------------------------------
__global__ void loss_kernel(const float* __restrict__ zi,
                            const float* __restrict__ zj, int B) {
    int warp = (blockIdx.x * blockDim.x + threadIdx.x) >> 5;
    int lane = threadIdx.x & 31;
    int N = 2 * B;
    if (warp >= N) return;
    int row = (warp < B) ? warp : (warp - B);
    const float* a = zi + (size_t)row * D;
    const float* b = zj + (size_t)row * D;
    float dot = 0.f;
#pragma unroll
    for (int q = 0; q < D / (32 * 4); q++) {
        float4 va = *(const float4*)(a + (q * 32 + lane) * 4);
        float4 vb = *(const float4*)(b + (q * 32 + lane) * 4);
        dot += va.x * vb.x + va.y * vb.y + va.z * vb.z + va.w * vb.w;
    }
#pragma unroll
    for (int o = 16; o > 0; o >>= 1) dot += __shfl_xor_sync(0xffffffffu, dot, o);
    if (lane == 0) {
        int prow = (warp < B) ? (warp + B) : (warp - B);
        float sim = dot * g_rinv[warp] * g_rinv[prow] * TEMP_INV;
        float denom = 0.f;
#pragma unroll
        for (int s = 0; s < NCHUNK; s++) denom += g_part[s * MAXN + warp];
        g_loss[warp] = logf(denom + 1e-8f) - sim;
    }
}

// ---------------------------------------------------------------------------
// 4) deterministic mean
// ---------------------------------------------------------------------------
__global__ void mean_kernel(float* __restrict__ out, int N) {
    __shared__ float red[256];
    int t = threadIdx.x;
    float s = 0.f;
    for (int i = t; i < N; i += 256) s += g_loss[i];
    red[t] = s;
    __syncthreads();
#pragma unroll
    for (int st = 128; st > 0; st >>= 1) {
        if (t < st) red[t] += red[t + st];
        __syncthreads();
    }
    if (t == 0) out[0] = red[0] / (float)N;
}

// ---------------------------------------------------------------------------
extern "C" void kernel_launch(void* const* d_in, const int* in_sizes, int n_in,
                              void* d_out, int out_size) {
    const float* zi = (const float*)d_in[0];
    const float* zj = (const float*)d_in[1];
    int B = in_sizes[0] / D;  // 4096
    int N = 2 * B;            // 8192

    cudaFuncSetAttribute(denom_kernel, cudaFuncAttributeMaxDynamicSharedMemorySize, SMEM_TOTAL);

    normalize_kernel<<<N, 128>>>(zi, zj, B);
    denom_kernel<<<NCTA, 256, SMEM_TOTAL>>>();
    loss_kernel<<<(N * 32 + 255) / 256, 256>>>(zi, zj, B);
    mean_kernel<<<1, 256>>>((float*)d_out, N);
}